// round 5
// baseline (speedup 1.0000x reference)
#include <cuda_runtime.h>
#include <cstdint>

// Problem constants
#define Bk 4
#define Ck 256
#define Hk 96
#define Wk 160
#define HWk (Hk * Wk)            // 15360
#define PPk 81

// Tiling: 16x8 pixel tile, 9 warps (one per dy), 4 px/thread, 2 CTAs/SM
#define TW 16
#define TH 8
#define KC 8                     // channels per chunk
#define NCH (Ck / KC)            // 32 chunks
#define NTHREADS 288             // 9 warps

// Shared strides: 48 floats => consecutive rows 16 banks apart; both LDS.128
// phases (2 rows x 4 xq per 8-lane phase) are conflict-free.
#define S0R 48                   // f0 row (16 used)
#define S1R 48                   // f1 halo row (24 used)
#define S0SZ (KC * TH * S0R)     // 3072 floats
#define S1SZ (KC * 16 * S1R)     // 6144 floats
#define BUFSZ (S0SZ + S1SZ)      // 9216 floats
#define SMEM_FLOATS (2 * BUFSZ)  // 18432 floats = 73728 B per CTA

__device__ __forceinline__ void cp_async16(unsigned saddr, const void* g) {
    asm volatile("cp.async.cg.shared.global [%0], [%1], 16;\n" ::"r"(saddr), "l"(g));
}
__device__ __forceinline__ void cp_async8(unsigned saddr, const void* g, int sz) {
    asm volatile("cp.async.ca.shared.global [%0], [%1], 8, %2;\n" ::"r"(saddr), "l"(g), "r"(sz));
}

__global__ void __launch_bounds__(NTHREADS, 2)
corr_kernel(const float* __restrict__ f0, const float* __restrict__ f1,
            float* __restrict__ out) {
    extern __shared__ float smem[];

    const int t    = threadIdx.x;
    const int x0   = blockIdx.x * TW;
    const int y0   = blockIdx.y * TH;
    const int b    = blockIdx.z;

    const int dyw  = t >> 5;                 // 0..8  -> dy = dyw-4
    const int lane = t & 31;
    const int r    = lane >> 2;              // 0..7 tile row
    const int xq   = lane & 3;               // 0..3
    const int xoff = xq * 4;                 // 0..12

    const float* f0b = f0 + (size_t)b * Ck * HWk;
    const float* f1b = f1 + (size_t)b * Ck * HWk;

    float acc[4][9];
#pragma unroll
    for (int p = 0; p < 4; p++)
#pragma unroll
        for (int j = 0; j < 9; j++) acc[p][j] = 0.0f;

    // ---- cooperative chunk prefetch (cp.async, zero-fill halo) ----
    auto prefetch = [&](int c0, int bsel) {
        float* s0 = smem + bsel * BUFSZ;
        float* s1 = s0 + S0SZ;
        // f0 tile: KC x TH x 16 -> 256 float4 transfers (threads 0..255)
        if (t < 256) {
            int c   = t >> 5;             // /32
            int rem = t & 31;
            int row = rem >> 2;
            int col = (rem & 3) << 2;
            const float* g = f0b + ((size_t)(c0 + c) * Hk + (y0 + row)) * Wk + x0 + col;
            unsigned sa = (unsigned)__cvta_generic_to_shared(s0 + (c * TH + row) * S0R + col);
            cp_async16(sa, g);
        }
        // f1 halo: KC x 16 x 24 -> 1536 float2 transfers
#pragma unroll
        for (int i = 0; i < 6; i++) {
            int idx = t + i * NTHREADS;
            if (idx < 1536) {
                int c    = idx / 192;
                int rem  = idx - c * 192;
                int row  = rem / 12;          // 0..15
                int col2 = rem - row * 12;    // 0..11
                int col  = col2 * 2;          // 0..22
                int gy   = y0 - 4 + row;
                int gx   = x0 - 4 + col;      // even; pair uniformly in/out of bounds
                bool ok  = (gy >= 0) && (gy < Hk) && (gx >= 0) && (gx < Wk);
                int gyc  = gy < 0 ? 0 : (gy >= Hk ? Hk - 1 : gy);
                int gxc  = gx < 0 ? 0 : (gx >= Wk ? Wk - 2 : gx);
                const float* g = f1b + ((size_t)(c0 + c) * Hk + gyc) * Wk + gxc;
                unsigned sa = (unsigned)__cvta_generic_to_shared(s1 + (c * 16 + row) * S1R + col);
                cp_async8(sa, g, ok ? 8 : 0);
            }
        }
        asm volatile("cp.async.commit_group;\n" ::: "memory");
    };

    prefetch(0, 0);

#pragma unroll 1
    for (int k = 0; k < NCH; k++) {
        if (k + 1 < NCH) {
            prefetch((k + 1) * KC, (k + 1) & 1);
            asm volatile("cp.async.wait_group 1;\n" ::: "memory");
        } else {
            asm volatile("cp.async.wait_group 0;\n" ::: "memory");
        }
        __syncthreads();

        const float* s0 = smem + (k & 1) * BUFSZ;
        const float* s1 = s0 + S0SZ;

#pragma unroll
        for (int c = 0; c < KC; c++) {
            // 12-float f1 window: halo row r+dyw, cols xoff..xoff+11
            float w[12];
            const float* wp = s1 + (c * 16 + r + dyw) * S1R + xoff;
            *(float4*)&w[0] = *(const float4*)&wp[0];
            *(float4*)&w[4] = *(const float4*)&wp[4];
            *(float4*)&w[8] = *(const float4*)&wp[8];
            // 4 f0 pixels
            float a[4];
            const float* fp = s0 + (c * TH + r) * S0R + xoff;
            *(float4*)&a[0] = *(const float4*)&fp[0];
#pragma unroll
            for (int p = 0; p < 4; p++)
#pragma unroll
                for (int j = 0; j < 9; j++)
                    acc[p][j] = fmaf(a[p], w[p + j], acc[p][j]);
        }
        __syncthreads();
    }

    // ---- epilogue: out[b, dyw*9+j, y0+r, x0+xoff+p] ----
    float* ob = out + (((size_t)b * PPk + dyw * 9) * Hk + (y0 + r)) * Wk + x0 + xoff;
#pragma unroll
    for (int j = 0; j < 9; j++) {
        float* p = ob + (size_t)j * HWk;
        *(float4*)p = make_float4(acc[0][j], acc[1][j], acc[2][j], acc[3][j]);
    }
}

extern "C" void kernel_launch(void* const* d_in, const int* in_sizes, int n_in,
                              void* d_out, int out_size) {
    const float* f0 = (const float*)d_in[0];
    const float* f1 = (const float*)d_in[1];
    float* out      = (float*)d_out;

    const int smem_bytes = SMEM_FLOATS * sizeof(float);  // 73728
    cudaFuncSetAttribute(corr_kernel, cudaFuncAttributeMaxDynamicSharedMemorySize, smem_bytes);

    dim3 grid(Wk / TW, Hk / TH, Bk);  // (10, 12, 4) = 480 blocks
    corr_kernel<<<grid, NTHREADS, smem_bytes>>>(f0, f1, out);
}

// round 6
// speedup vs baseline: 1.0044x; 1.0044x over previous
#include <cuda_runtime.h>
#include <cstdint>

// Problem constants
#define Bk 4
#define Ck 256
#define Hk 96
#define Wk 160
#define HWk (Hk * Wk)            // 15360
#define PPk 81

// Tiling: 16x8 pixel tile, 9 warps (one per dy), 4 px/thread, 2 CTAs/SM
#define TW 16
#define TH 8
#define KC 8                     // channels per chunk
#define NCH (Ck / KC)            // 32 chunks
#define NTHREADS 288             // 9 warps

// Shared strides: 48 floats => consecutive rows 16 banks apart; both LDS.128
// phases (2 rows x 4 xq per 8-lane phase) are conflict-free.
#define S0R 48                   // f0 row (16 used)
#define S1R 48                   // f1 halo row (24 used)
#define S0SZ (KC * TH * S0R)     // 3072 floats
#define S1SZ (KC * 16 * S1R)     // 6144 floats
#define BUFSZ (S0SZ + S1SZ)      // 9216 floats
#define SMEM_FLOATS (2 * BUFSZ)  // 18432 floats = 73728 B per CTA

__device__ __forceinline__ void cp_async16(unsigned saddr, const void* g) {
    asm volatile("cp.async.cg.shared.global [%0], [%1], 16;\n" ::"r"(saddr), "l"(g));
}
__device__ __forceinline__ void cp_async8(unsigned saddr, const void* g, int sz) {
    asm volatile("cp.async.ca.shared.global [%0], [%1], 8, %2;\n" ::"r"(saddr), "l"(g), "r"(sz));
}

__global__ void __launch_bounds__(NTHREADS, 2)
corr_kernel(const float* __restrict__ f0, const float* __restrict__ f1,
            float* __restrict__ out) {
    extern __shared__ float smem[];

    const int t    = threadIdx.x;
    const int x0   = blockIdx.x * TW;
    const int y0   = blockIdx.y * TH;
    const int b    = blockIdx.z;

    const int dyw  = t >> 5;                 // 0..8  -> dy = dyw-4
    const int lane = t & 31;
    const int r    = lane >> 2;              // 0..7 tile row
    const int xq   = lane & 3;               // 0..3
    const int xoff = xq * 4;                 // 0..12

    const float* f0b = f0 + (size_t)b * Ck * HWk;
    const float* f1b = f1 + (size_t)b * Ck * HWk;

    float acc[4][9];
#pragma unroll
    for (int p = 0; p < 4; p++)
#pragma unroll
        for (int j = 0; j < 9; j++) acc[p][j] = 0.0f;

    // ---- cooperative chunk prefetch (cp.async, zero-fill halo) ----
    auto prefetch = [&](int c0, int bsel) {
        float* s0 = smem + bsel * BUFSZ;
        float* s1 = s0 + S0SZ;
        // f0 tile: KC x TH x 16 -> 256 float4 transfers (threads 0..255)
        if (t < 256) {
            int c   = t >> 5;             // /32
            int rem = t & 31;
            int row = rem >> 2;
            int col = (rem & 3) << 2;
            const float* g = f0b + ((size_t)(c0 + c) * Hk + (y0 + row)) * Wk + x0 + col;
            unsigned sa = (unsigned)__cvta_generic_to_shared(s0 + (c * TH + row) * S0R + col);
            cp_async16(sa, g);
        }
        // f1 halo: KC x 16 x 24 -> 1536 float2 transfers
#pragma unroll
        for (int i = 0; i < 6; i++) {
            int idx = t + i * NTHREADS;
            if (idx < 1536) {
                int c    = idx / 192;
                int rem  = idx - c * 192;
                int row  = rem / 12;          // 0..15
                int col2 = rem - row * 12;    // 0..11
                int col  = col2 * 2;          // 0..22
                int gy   = y0 - 4 + row;
                int gx   = x0 - 4 + col;      // even; pair uniformly in/out of bounds
                bool ok  = (gy >= 0) && (gy < Hk) && (gx >= 0) && (gx < Wk);
                int gyc  = gy < 0 ? 0 : (gy >= Hk ? Hk - 1 : gy);
                int gxc  = gx < 0 ? 0 : (gx >= Wk ? Wk - 2 : gx);
                const float* g = f1b + ((size_t)(c0 + c) * Hk + gyc) * Wk + gxc;
                unsigned sa = (unsigned)__cvta_generic_to_shared(s1 + (c * 16 + row) * S1R + col);
                cp_async8(sa, g, ok ? 8 : 0);
            }
        }
        asm volatile("cp.async.commit_group;\n" ::: "memory");
    };

    prefetch(0, 0);

#pragma unroll 1
    for (int k = 0; k < NCH; k++) {
        if (k + 1 < NCH) {
            prefetch((k + 1) * KC, (k + 1) & 1);
            asm volatile("cp.async.wait_group 1;\n" ::: "memory");
        } else {
            asm volatile("cp.async.wait_group 0;\n" ::: "memory");
        }
        __syncthreads();

        const float* s0 = smem + (k & 1) * BUFSZ;
        const float* s1 = s0 + S0SZ;

#pragma unroll
        for (int c = 0; c < KC; c++) {
            // 12-float f1 window: halo row r+dyw, cols xoff..xoff+11
            float w[12];
            const float* wp = s1 + (c * 16 + r + dyw) * S1R + xoff;
            *(float4*)&w[0] = *(const float4*)&wp[0];
            *(float4*)&w[4] = *(const float4*)&wp[4];
            *(float4*)&w[8] = *(const float4*)&wp[8];
            // 4 f0 pixels
            float a[4];
            const float* fp = s0 + (c * TH + r) * S0R + xoff;
            *(float4*)&a[0] = *(const float4*)&fp[0];
#pragma unroll
            for (int p = 0; p < 4; p++)
#pragma unroll
                for (int j = 0; j < 9; j++)
                    acc[p][j] = fmaf(a[p], w[p + j], acc[p][j]);
        }
        __syncthreads();
    }

    // ---- epilogue: out[b, dyw*9+j, y0+r, x0+xoff+p] ----
    float* ob = out + (((size_t)b * PPk + dyw * 9) * Hk + (y0 + r)) * Wk + x0 + xoff;
#pragma unroll
    for (int j = 0; j < 9; j++) {
        float* p = ob + (size_t)j * HWk;
        *(float4*)p = make_float4(acc[0][j], acc[1][j], acc[2][j], acc[3][j]);
    }
}

extern "C" void kernel_launch(void* const* d_in, const int* in_sizes, int n_in,
                              void* d_out, int out_size) {
    const float* f0 = (const float*)d_in[0];
    const float* f1 = (const float*)d_in[1];
    float* out      = (float*)d_out;

    const int smem_bytes = SMEM_FLOATS * sizeof(float);  // 73728
    cudaFuncSetAttribute(corr_kernel, cudaFuncAttributeMaxDynamicSharedMemorySize, smem_bytes);

    dim3 grid(Wk / TW, Hk / TH, Bk);  // (10, 12, 4) = 480 blocks
    corr_kernel<<<grid, NTHREADS, smem_bytes>>>(f0, f1, out);
}

// round 7
// speedup vs baseline: 1.0072x; 1.0027x over previous
#include <cuda_runtime.h>
#include <cstdint>

// Problem constants
#define Bk 4
#define Ck 256
#define Hk 96
#define Wk 160
#define HWk (Hk * Wk)            // 15360
#define PPk 81

// Tiling: 16x8 pixel tile, 9 warps (one per dy), 4 px/thread, 2 CTAs/SM
#define TW 16
#define TH 8
#define KC 8                     // channels per chunk
#define NCH (Ck / KC)            // 32 chunks
#define NTHREADS 288             // 9 warps

// Shared strides: 48 floats => consecutive rows 16 banks apart; both LDS.128
// phases (2 rows x 4 xq per 8-lane phase) are conflict-free.
#define S0R 48                   // f0 row (16 used)
#define S1R 48                   // f1 halo row (24 used)
#define S0SZ (KC * TH * S0R)     // 3072 floats
#define S1SZ (KC * 16 * S1R)     // 6144 floats
#define BUFSZ (S0SZ + S1SZ)      // 9216 floats
#define SMEM_FLOATS (2 * BUFSZ)  // 18432 floats = 73728 B per CTA

__device__ __forceinline__ void cp_async16(unsigned saddr, const void* g) {
    asm volatile("cp.async.cg.shared.global [%0], [%1], 16;\n" ::"r"(saddr), "l"(g));
}
__device__ __forceinline__ void cp_async8(unsigned saddr, const void* g, int sz) {
    asm volatile("cp.async.ca.shared.global [%0], [%1], 8, %2;\n" ::"r"(saddr), "l"(g), "r"(sz));
}

__global__ void __launch_bounds__(NTHREADS, 2)
corr_kernel(const float* __restrict__ f0, const float* __restrict__ f1,
            float* __restrict__ out) {
    extern __shared__ float smem[];

    const int t    = threadIdx.x;
    const int x0   = blockIdx.x * TW;
    const int y0   = blockIdx.y * TH;
    const int b    = blockIdx.z;

    const int dyw  = t >> 5;                 // 0..8  -> dy = dyw-4
    const int lane = t & 31;
    const int r    = lane >> 2;              // 0..7 tile row
    const int xq   = lane & 3;               // 0..3
    const int xoff = xq * 4;                 // 0..12

    const float* f0b = f0 + (size_t)b * Ck * HWk;
    const float* f1b = f1 + (size_t)b * Ck * HWk;

    float acc[4][9];
#pragma unroll
    for (int p = 0; p < 4; p++)
#pragma unroll
        for (int j = 0; j < 9; j++) acc[p][j] = 0.0f;

    // ---- cooperative chunk prefetch (cp.async, zero-fill halo) ----
    auto prefetch = [&](int c0, int bsel) {
        float* s0 = smem + bsel * BUFSZ;
        float* s1 = s0 + S0SZ;
        // f0 tile: KC x TH x 16 -> 256 float4 transfers (threads 0..255)
        if (t < 256) {
            int c   = t >> 5;             // /32
            int rem = t & 31;
            int row = rem >> 2;
            int col = (rem & 3) << 2;
            const float* g = f0b + ((size_t)(c0 + c) * Hk + (y0 + row)) * Wk + x0 + col;
            unsigned sa = (unsigned)__cvta_generic_to_shared(s0 + (c * TH + row) * S0R + col);
            cp_async16(sa, g);
        }
        // f1 halo: KC x 16 x 24 -> 1536 float2 transfers
#pragma unroll
        for (int i = 0; i < 6; i++) {
            int idx = t + i * NTHREADS;
            if (idx < 1536) {
                int c    = idx / 192;
                int rem  = idx - c * 192;
                int row  = rem / 12;          // 0..15
                int col2 = rem - row * 12;    // 0..11
                int col  = col2 * 2;          // 0..22
                int gy   = y0 - 4 + row;
                int gx   = x0 - 4 + col;      // even; pair uniformly in/out of bounds
                bool ok  = (gy >= 0) && (gy < Hk) && (gx >= 0) && (gx < Wk);
                int gyc  = gy < 0 ? 0 : (gy >= Hk ? Hk - 1 : gy);
                int gxc  = gx < 0 ? 0 : (gx >= Wk ? Wk - 2 : gx);
                const float* g = f1b + ((size_t)(c0 + c) * Hk + gyc) * Wk + gxc;
                unsigned sa = (unsigned)__cvta_generic_to_shared(s1 + (c * 16 + row) * S1R + col);
                cp_async8(sa, g, ok ? 8 : 0);
            }
        }
        asm volatile("cp.async.commit_group;\n" ::: "memory");
    };

    prefetch(0, 0);

#pragma unroll 1
    for (int k = 0; k < NCH; k++) {
        if (k + 1 < NCH) {
            prefetch((k + 1) * KC, (k + 1) & 1);
            asm volatile("cp.async.wait_group 1;\n" ::: "memory");
        } else {
            asm volatile("cp.async.wait_group 0;\n" ::: "memory");
        }
        __syncthreads();

        const float* s0 = smem + (k & 1) * BUFSZ;
        const float* s1 = s0 + S0SZ;

#pragma unroll
        for (int c = 0; c < KC; c++) {
            // 12-float f1 window: halo row r+dyw, cols xoff..xoff+11
            float w[12];
            const float* wp = s1 + (c * 16 + r + dyw) * S1R + xoff;
            *(float4*)&w[0] = *(const float4*)&wp[0];
            *(float4*)&w[4] = *(const float4*)&wp[4];
            *(float4*)&w[8] = *(const float4*)&wp[8];
            // 4 f0 pixels
            float a[4];
            const float* fp = s0 + (c * TH + r) * S0R + xoff;
            *(float4*)&a[0] = *(const float4*)&fp[0];
#pragma unroll
            for (int p = 0; p < 4; p++)
#pragma unroll
                for (int j = 0; j < 9; j++)
                    acc[p][j] = fmaf(a[p], w[p + j], acc[p][j]);
        }
        __syncthreads();
    }

    // ---- epilogue: out[b, dyw*9+j, y0+r, x0+xoff+p] ----
    float* ob = out + (((size_t)b * PPk + dyw * 9) * Hk + (y0 + r)) * Wk + x0 + xoff;
#pragma unroll
    for (int j = 0; j < 9; j++) {
        float* p = ob + (size_t)j * HWk;
        *(float4*)p = make_float4(acc[0][j], acc[1][j], acc[2][j], acc[3][j]);
    }
}

extern "C" void kernel_launch(void* const* d_in, const int* in_sizes, int n_in,
                              void* d_out, int out_size) {
    const float* f0 = (const float*)d_in[0];
    const float* f1 = (const float*)d_in[1];
    float* out      = (float*)d_out;

    const int smem_bytes = SMEM_FLOATS * sizeof(float);  // 73728
    cudaFuncSetAttribute(corr_kernel, cudaFuncAttributeMaxDynamicSharedMemorySize, smem_bytes);

    dim3 grid(Wk / TW, Hk / TH, Bk);  // (10, 12, 4) = 480 blocks
    corr_kernel<<<grid, NTHREADS, smem_bytes>>>(f0, f1, out);
}